// round 7
// baseline (speedup 1.0000x reference)
#include <cuda_runtime.h>
#include <cuda_bf16.h>
#include <cstdint>

// CRF loss: out[b] = logZ(b) - gold_score(b).  B=2048, L=512, T=32.
// One warp (= one block) per batch; lane j owns state j.
//
// Scaled-prob-space recurrence (Mx = exp(transition), w = exp(emit)):
//   a'[j] = (sum_i a[i] * Mx[i][j]) * w[j] / a_prev[0]
//   M    += log(a_prev[0])
// Invariant: d[j] = M + log(a[j]).  Self-normalizing each step by a_prev[0]
// (read for free as the first LDS of the mat-vec) keeps a within e^(+-40).
// No exp/log/shfl on the serial critical path; mat-vec uses packed f32x2 FMAs.
// Final: logZ = M + log(sum_j a[j]).
//
// (Resubmission of R3 kernel: previous bench aborted on GB300 container
// infra failure, not on the kernel.)

#define CRF_B 2048
#define CRF_L 512
#define CRF_T 32
#define CHUNK 8

__device__ __forceinline__ unsigned smem_u32(const void* p) {
    return (unsigned)__cvta_generic_to_shared(p);
}

__global__ __launch_bounds__(32)
void crf_forward_kernel(const float* __restrict__ emit,      // (B, L, T)
                        const float* __restrict__ trans,     // (T, T)
                        const int*   __restrict__ tags,      // (B, L)
                        const int*   __restrict__ lengths,   // (B,)
                        float*       __restrict__ out)       // (B,)
{
    const unsigned FULL = 0xffffffffu;
    __shared__ __align__(16) float ebuf[2][CHUNK * CRF_T];   // staged emit (2x1KB)
    __shared__ __align__(16) float pbuf[2][CRF_T];           // alpha double buffer

    const int b    = blockIdx.x;
    const int lane = threadIdx.x;
    const int len  = lengths[b];

    // Mx column for this lane, packed as 16 f32x2 pairs over i:
    // Mp[q] = ( exp(trans[2q][lane]), exp(trans[2q+1][lane]) )
    unsigned long long Mp[16];
#pragma unroll
    for (int q = 0; q < 16; q++) {
        float m0 = __expf(__ldg(&trans[(2 * q + 0) * CRF_T + lane]));
        float m1 = __expf(__ldg(&trans[(2 * q + 1) * CRF_T + lane]));
        asm("mov.b64 %0, {%1, %2};" : "=l"(Mp[q]) : "f"(m0), "f"(m1));
    }

    const float* erow = emit + (size_t)b * CRF_L * CRF_T;
    const int nch = (len + CHUNK - 1) / CHUNK;

    auto issue_chunk = [&](int c) {
        if (c < nch) {
            const char* src = (const char*)(erow + c * (CHUNK * CRF_T));
            unsigned dst = smem_u32(&ebuf[c & 1][0]);
            asm volatile("cp.async.cg.shared.global [%0], [%1], 16;\n"
                         :: "r"(dst + lane * 16), "l"(src + lane * 16));
            asm volatile("cp.async.cg.shared.global [%0], [%1], 16;\n"
                         :: "r"(dst + 512 + lane * 16), "l"(src + 512 + lane * 16));
        }
        asm volatile("cp.async.commit_group;\n");
    };

    issue_chunk(0);
    issue_chunk(1);

    const unsigned pb0 = smem_u32(&pbuf[0][0]);
    const unsigned pb1 = smem_u32(&pbuf[1][0]);

    float a   = 0.f;   // this lane's alpha
    float Ml2 = 0.f;   // running scale, in log2

    for (int c = 0; c < nch; c++) {
        asm volatile("cp.async.wait_group 1;\n" ::: "memory");
        __syncwarp();
        const float* E = &ebuf[c & 1][0];

        // Batched off-chain exp of the emit rows in this chunk.
        float w[CHUNK];
#pragma unroll
        for (int k = 0; k < CHUNK; k++)
            w[k] = __expf(E[k * CRF_T + lane]);

        issue_chunk(c + 2);   // E dead after w[]; safe to refill this buffer

#pragma unroll
        for (int k = 0; k < CHUNK; k++) {
            const int row = c * CHUNK + k;
            if (row == 0) {
                a = w[0];                  // a_0 = exp(e_0), M_0 = 0
                pbuf[0][lane] = a;
                __syncwarp();
            } else if (row < len) {        // warp-uniform predicate
                const unsigned pin  = ((row - 1) & 1) ? pb1 : pb0;
                const unsigned pout = (row & 1)       ? pb1 : pb0;

                unsigned long long acc0 = 0ull, acc1 = 0ull, x, y;
                float g;
                // q = 0: also extract g = a_prev[0]
                asm volatile("ld.shared.v2.u64 {%0, %1}, [%2];"
                             : "=l"(x), "=l"(y) : "r"(pin));
                { float ghi;
                  asm("mov.b64 {%0, %1}, %2;" : "=f"(g), "=f"(ghi) : "l"(x)); }
                asm("fma.rn.f32x2 %0, %1, %2, %0;" : "+l"(acc0) : "l"(x), "l"(Mp[0]));
                asm("fma.rn.f32x2 %0, %1, %2, %0;" : "+l"(acc1) : "l"(y), "l"(Mp[1]));
#pragma unroll
                for (int q = 1; q < 8; q++) {
                    asm volatile("ld.shared.v2.u64 {%0, %1}, [%2];"
                                 : "=l"(x), "=l"(y) : "r"(pin + q * 16));
                    asm("fma.rn.f32x2 %0, %1, %2, %0;" : "+l"(acc0) : "l"(x), "l"(Mp[2 * q + 0]));
                    asm("fma.rn.f32x2 %0, %1, %2, %0;" : "+l"(acc1) : "l"(y), "l"(Mp[2 * q + 1]));
                }
                // Off-chain: reciprocal of g and scale bookkeeping
                float rg; asm("rcp.approx.f32 %0, %1;" : "=f"(rg) : "f"(g));
                const float wr = w[k] * rg;
                Ml2 += __log2f(g);
                // Tail: pairwise add, unpack, scale
                asm("add.rn.f32x2 %0, %0, %1;" : "+l"(acc0) : "l"(acc1));
                float s0, s1;
                asm("mov.b64 {%0, %1}, %2;" : "=f"(s0), "=f"(s1) : "l"(acc0));
                a = (s0 + s1) * wr;
                asm volatile("st.shared.f32 [%0], %1;" :: "r"(pout + lane * 4), "f"(a));
                __syncwarp();
            }
        }
    }

    // logZ = M + log(sum_j a[j])
    float sum = a;
#pragma unroll
    for (int off = 16; off; off >>= 1)
        sum += __shfl_xor_sync(FULL, sum, off);
    const float logz = Ml2 * 0.6931471805599453f + __logf(sum);

    // Gold-path score
    const int* trow = tags + b * CRF_L;
    float gs = 0.f;
    for (int l = lane; l < len; l += 32) {
        int tg = __ldg(&trow[l]);
        gs += __ldg(&erow[l * CRF_T + tg]);
        if (l >= 1) {
            int tp = __ldg(&trow[l - 1]);
            gs += __ldg(&trans[tp * CRF_T + tg]);
        }
    }
#pragma unroll
    for (int off = 16; off; off >>= 1)
        gs += __shfl_xor_sync(FULL, gs, off);

    if (lane == 0) out[b] = logz - gs;
}

extern "C" void kernel_launch(void* const* d_in, const int* in_sizes, int n_in,
                              void* d_out, int out_size)
{
    const float* emit    = (const float*)d_in[0];
    const float* trans   = (const float*)d_in[1];
    const int*   tags    = (const int*)d_in[2];
    const int*   lengths = (const int*)d_in[3];
    float*       out     = (float*)d_out;

    (void)in_sizes; (void)n_in; (void)out_size;

    crf_forward_kernel<<<CRF_B, 32>>>(emit, trans, tags, lengths, out);
}